// round 15
// baseline (speedup 1.0000x reference)
#include <cuda_runtime.h>
#include <math.h>

#define BB 8
#define VV 6890
#define FF 13776
#define NP 4096
#define EPSF 1e-12f
#define NFB ((BB * FF + 255) / 256)  // 431 k_faces blocks
#define RBLK 128                     // row blocks per batch (4096/32)
#define NPOST ((5 * BB * NP) / 256)  // 640 k_post blocks (rows + 4x cols)
#define SMEM_CDF (FF * sizeof(float))

typedef unsigned long long ull;

// ---------------- device scratch (no allocations allowed) ----------------
__device__ float        g_area[BB * FF];           // per-face raw areas
__device__ float4       g_fn [BB * FF];            // per-face unit normals
__device__ float4       g_pts[2 * BB * NP];        // sampled points, w=|p|^2
__device__ float4       g_nrm[2 * BB * NP];        // sampled normals
__device__ unsigned int g_rowm[BB * NP];           // per-row mangled min (bits)
__device__ float        g_colp[BB * RBLK * NP];    // col-min partials (16.8MB)
__device__ float        g_edge[NFB];               // edge-loss block partials
__device__ float        g_part[2 * NPOST];         // k_post block partials (d,n)
__device__ unsigned int g_cnt;                     // last-block ticket (self-reset)

// ---------------- packed f32x2 helpers ----------------
__device__ __forceinline__ ull pk2(float lo, float hi) {
    ull r;
    asm("mov.b64 %0, {%1, %2};" : "=l"(r) : "f"(lo), "f"(hi));
    return r;
}
__device__ __forceinline__ float2 unpk(ull v) {
    float2 f;
    asm("mov.b64 {%0, %1}, %2;" : "=f"(f.x), "=f"(f.y) : "l"(v));
    return f;
}
__device__ __forceinline__ ull fma2(ull a, ull b, ull c) {
    ull d;
    asm("fma.rn.f32x2 %0, %1, %2, %3;" : "=l"(d) : "l"(a), "l"(b), "l"(c));
    return d;
}
__device__ __forceinline__ ull add2(ull a, ull b) {
    ull d;
    asm("add.rn.f32x2 %0, %1, %2;" : "=l"(d) : "l"(a), "l"(b));
    return d;
}
// packed min emulated with two scalar FMNMX on the register-pair halves
__device__ __forceinline__ ull min2(ull a, ull b) {
    float2 fa = unpk(a), fb = unpk(b);
    return pk2(fminf(fa.x, fb.x), fminf(fa.y, fb.y));
}
__device__ __forceinline__ ull shfl_xor64_w8(ull v, int m) {
    unsigned lo = (unsigned)v, hi = (unsigned)(v >> 32);
    lo = __shfl_xor_sync(0xffffffffu, lo, m, 8);
    hi = __shfl_xor_sync(0xffffffffu, hi, m, 8);
    return ((ull)hi << 32) | lo;
}

// ---------------- kernels ----------------

// Per (b,f): raw area, unit normal, edge partial per block.
__global__ void k_faces(const float* __restrict__ verts,
                        const int*   __restrict__ faces) {
    int id = blockIdx.x * blockDim.x + threadIdx.x;
    float esum = 0.f;
    if (id < BB * FF) {
        int b = id / FF, f = id % FF;
        int i0 = faces[f * 3 + 0];
        int i1 = faces[f * 3 + 1];
        int i2 = faces[f * 3 + 2];
        const float* vb = verts + (size_t)b * VV * 3;
        float ax = vb[i0*3+0], ay = vb[i0*3+1], az = vb[i0*3+2];
        float bx = vb[i1*3+0], by = vb[i1*3+1], bz = vb[i1*3+2];
        float cx = vb[i2*3+0], cy = vb[i2*3+1], cz = vb[i2*3+2];
        float ux = bx-ax, uy = by-ay, uz = bz-az;   // v1-v0
        float wx = cx-ax, wy = cy-ay, wz = cz-az;   // v2-v0
        float crx = uy*wz - uz*wy;
        float cry = uz*wx - ux*wz;
        float crz = ux*wy - uy*wx;
        float cn  = sqrtf(crx*crx + cry*cry + crz*crz);
        g_area[id] = 0.5f * cn;
        float inv = 1.f / (cn + EPSF);
        g_fn[id]  = make_float4(crx*inv, cry*inv, crz*inv, 0.f);
        float ex = bx-cx, ey = by-cy, ez = bz-cz;   // v1-v2
        esum = (ux*ux + uy*uy + uz*uz)
             + (ex*ex + ey*ey + ez*ez)
             + (wx*wx + wy*wy + wz*wz);
    }
    __shared__ float sred[256];
    sred[threadIdx.x] = esum;
    __syncthreads();
    for (int s = 128; s > 0; s >>= 1) {
        if (threadIdx.x < s) sred[threadIdx.x] += sred[threadIdx.x + s];
        __syncthreads();
    }
    if (threadIdx.x == 0) g_edge[blockIdx.x] = sred[0];
}

// Sample points. grid (16 chunks, 8 batches, 2 sets), block 256.
// Each block scans its batch's raw areas into a dynamic-smem normalized CDF
// (replaces the separate k_scan kernel), then binary-searches in smem.
__global__ void k_sample(const float* __restrict__ verts,
                         const int*   __restrict__ faces,
                         const float* __restrict__ rp,
                         const float* __restrict__ rg) {
    extern __shared__ float scdf[];                // FF floats
    int set = blockIdx.z;
    int b   = blockIdx.y;
    int t   = threadIdx.x;
    int lane = t & 31, warp = t >> 5;              // 8 warps
    int n   = blockIdx.x * 256 + t;

    // ---- in-block scan: raw areas -> normalized CDF in smem ----
    const float* area = g_area + (size_t)b * FF;
    const int CH = (FF + 255) / 256;               // 54
    int beg = t * CH;
    int end = min(beg + CH, FF);
    float s = 0.f;
    for (int i = beg; i < end; i++) { s += area[i]; scdf[i] = s; }

    float ws = s;
    #pragma unroll
    for (int off = 1; off < 32; off <<= 1) {
        float v = __shfl_up_sync(0xffffffffu, ws, off);
        if (lane >= off) ws += v;
    }
    __shared__ float wsum[8];
    __shared__ float wpre[9];
    if (lane == 31) wsum[warp] = ws;
    __syncthreads();
    if (warp == 0) {
        float x = (lane < 8) ? wsum[lane] : 0.f;
        #pragma unroll
        for (int off = 1; off < 8; off <<= 1) {
            float v = __shfl_up_sync(0xffffffffu, x, off, 8);
            if ((lane & 7) >= off) x += v;
        }
        if (lane < 8) wpre[lane + 1] = x;
        if (lane == 0) wpre[0] = 0.f;
    }
    __syncthreads();
    float total = wpre[8];
    float excl  = wpre[warp] + (ws - s);
    float scale = 1.f / (total + EPSF);
    for (int i = beg; i < end; i++) scdf[i] = (scdf[i] + excl) * scale;
    __syncthreads();

    // ---- sample ----
    const float* rnd = (set ? rg : rp) + ((size_t)b * NP + n) * 3;
    float u = rnd[0], r1 = rnd[1], r2 = rnd[2];

    // searchsorted side='left' over smem CDF
    int lo = 0, hi = FF;
    while (lo < hi) {
        int m = (lo + hi) >> 1;
        if (scdf[m] < u) lo = m + 1; else hi = m;
    }
    int idx = min(lo, FF - 1);

    int i0 = faces[idx*3+0], i1 = faces[idx*3+1], i2 = faces[idx*3+2];
    const float* vb = verts + (size_t)b * VV * 3;
    float su = sqrtf(r1);
    float w0 = 1.f - su;
    float w1 = su * (1.f - r2);
    float w2 = su * r2;
    float x = w0*vb[i0*3+0] + w1*vb[i1*3+0] + w2*vb[i2*3+0];
    float y = w0*vb[i0*3+1] + w1*vb[i1*3+1] + w2*vb[i2*3+1];
    float z = w0*vb[i0*3+2] + w1*vb[i1*3+2] + w2*vb[i2*3+2];
    int out = set * BB * NP + b * NP + n;
    g_pts[out] = make_float4(x, y, z, x*x + y*y + z*z);
    g_nrm[out] = g_fn[(size_t)b * FF + idx];
}

// Fused chamfer (proven R12 config): packed f32x2 FMA chain + double-buffered
// tiles + width-8 shuffle col reduce + plain float4 stores of col partials.
// grid (RBLK=128, BB), block 256: 32 rows x 4096 cols per block.
__global__ void __launch_bounds__(256) k_cham() {
    const int b   = blockIdx.y;
    const int rb  = blockIdx.x * 32;
    const int tid = threadIdx.x;
    const int tx  = tid >> 3;      // 0..31 col group
    const int ty  = tid & 7;       // 0..7 row group
    const float4* __restrict__ P = g_pts + (size_t)b * NP;
    const float4* __restrict__ Q = g_pts + BB * NP + (size_t)b * NP;

    __shared__ __align__(16) float sqx[2][128];
    __shared__ __align__(16) float sqy[2][128];
    __shared__ __align__(16) float sqz[2][128];
    __shared__ __align__(16) float sqw[2][128];
    __shared__ unsigned int srow[32][33];

    const ull INF2 = pk2(__int_as_float(0x7F800000), __int_as_float(0x7F800000));

    ull px2d[4], py2d[4], pz2d[4], pwd[4], rowb2[4];
    #pragma unroll
    for (int i = 0; i < 4; i++) {
        float4 p = P[rb + ty * 4 + i];
        float vx = -2.f * p.x, vy = -2.f * p.y, vz = -2.f * p.z;
        px2d[i] = pk2(vx, vx);
        py2d[i] = pk2(vy, vy);
        pz2d[i] = pk2(vz, vz);
        pwd[i]  = pk2(p.w, p.w);
        rowb2[i] = INF2;
    }
    ull cbase0 = ((ull)(unsigned)(tx * 4 + 1) << 32) | (unsigned)(tx * 4);
    ull cbase1 = cbase0 + 0x0000000200000002ULL;

    if (tid < 128) {
        float4 q = Q[tid];
        sqx[0][tid] = q.x; sqy[0][tid] = q.y; sqz[0][tid] = q.z; sqw[0][tid] = q.w;
    }
    __syncthreads();

    for (int t = 0; t < 32; t++) {
        float4 nq;
        if (t < 31 && tid < 128) nq = Q[(t + 1) * 128 + tid];
        const int cur = t & 1;
        ull ctpk  = (ull)(unsigned)(t * 128) * 0x0000000100000001ULL;
        ull colb0 = INF2, colb1 = INF2;

        {
            int c = tx * 4;
            ull qx0 = *(const ull*)&sqx[cur][c];
            ull qy0 = *(const ull*)&sqy[cur][c];
            ull qz0 = *(const ull*)&sqz[cur][c];
            ull qw0 = *(const ull*)&sqw[cur][c];
            ull qx1 = *(const ull*)&sqx[cur][c + 2];
            ull qy1 = *(const ull*)&sqy[cur][c + 2];
            ull qz1 = *(const ull*)&sqz[cur][c + 2];
            ull qw1 = *(const ull*)&sqw[cur][c + 2];
            ull cp0 = cbase0 + ctpk;
            ull cp1 = cbase1 + ctpk;
            #pragma unroll
            for (int i = 0; i < 4; i++) {
                ull d0 = add2(fma2(px2d[i], qx0,
                           fma2(py2d[i], qy0,
                           fma2(pz2d[i], qz0, qw0))), pwd[i]);
                ull m0 = (d0 & 0xFFFFF000FFFFF000ULL) | cp0;
                rowb2[i] = min2(rowb2[i], m0);
                colb0    = min2(colb0, d0);
                ull d1 = add2(fma2(px2d[i], qx1,
                           fma2(py2d[i], qy1,
                           fma2(pz2d[i], qz1, qw1))), pwd[i]);
                ull m1 = (d1 & 0xFFFFF000FFFFF000ULL) | cp1;
                rowb2[i] = min2(rowb2[i], m1);
                colb1    = min2(colb1, d1);
            }
        }
        colb0 = min2(colb0, shfl_xor64_w8(colb0, 4));
        colb0 = min2(colb0, shfl_xor64_w8(colb0, 2));
        colb0 = min2(colb0, shfl_xor64_w8(colb0, 1));
        colb1 = min2(colb1, shfl_xor64_w8(colb1, 4));
        colb1 = min2(colb1, shfl_xor64_w8(colb1, 2));
        colb1 = min2(colb1, shfl_xor64_w8(colb1, 1));
        if (ty == 0) {
            int base = ((b * RBLK + blockIdx.x) << 12) + t * 128 + tx * 4;
            float2 f0 = unpk(colb0), f1 = unpk(colb1);
            *(float4*)&g_colp[base] = make_float4(f0.x, f0.y, f1.x, f1.y);
        }
        if (t < 31 && tid < 128) {
            const int nb = (t + 1) & 1;
            sqx[nb][tid] = nq.x; sqy[nb][tid] = nq.y;
            sqz[nb][tid] = nq.z; sqw[nb][tid] = nq.w;
        }
        __syncthreads();
    }

    #pragma unroll
    for (int i = 0; i < 4; i++) {
        float2 f = unpk(rowb2[i]);
        srow[ty * 4 + i][tx] = __float_as_uint(fminf(f.x, f.y));
    }
    __syncthreads();
    if (tid < 32) {
        float best = __uint_as_float(srow[tid][0]);
        #pragma unroll
        for (int k = 1; k < 32; k++)
            best = fminf(best, __uint_as_float(srow[tid][k]));
        g_rowm[(size_t)b * NP + rb + tid] = __float_as_uint(best);
    }
}

// Rows: decode argmin, recompute exact distance + normal loss.
// Cols: 4 lanes per column (k split 32 each, full unroll, 4 accumulators),
// folded by in-warp shfl mins. Last block folds everything.
__global__ void k_post(float* out) {
    int gid = blockIdx.x * 256 + threadIdx.x;   // 0 .. 5*BB*NP
    float sd = 0.f, sn = 0.f;
    if (gid < BB * NP) {                        // rows -> dist1 + normals
        int b = gid >> 12;
        unsigned int m = g_rowm[gid];
        int col = m & 0xFFF;
        int qi  = BB * NP + (b << 12) + col;
        float4 p = g_pts[gid];
        float4 q = g_pts[qi];
        sd = p.w + q.w - 2.f * (p.x*q.x + p.y*q.y + p.z*q.z);
        float4 pn = g_nrm[gid];
        float4 qn = g_nrm[qi];
        sn = 1.f - fabsf(pn.x*qn.x + pn.y*qn.y + pn.z*qn.z);
    } else {                                    // cols -> dist2 (4 lanes/col)
        int lane = threadIdx.x & 31;
        int wq   = (gid - BB * NP) >> 5;        // warp id in col section
        int flat = wq * 8 + (lane & 7);         // column (batch-flattened)
        int q    = lane >> 3;                   // k-quarter 0..3
        int b    = flat >> 12, col = flat & 4095;
        const float* cp = g_colp + ((size_t)(b * RBLK + q * 32) << 12) + col;
        float b0 = __int_as_float(0x7F800000), b1 = b0, b2 = b0, b3 = b0;
        #pragma unroll
        for (int k = 0; k < 32; k += 4) {
            b0 = fminf(b0, cp[(size_t)(k + 0) << 12]);
            b1 = fminf(b1, cp[(size_t)(k + 1) << 12]);
            b2 = fminf(b2, cp[(size_t)(k + 2) << 12]);
            b3 = fminf(b3, cp[(size_t)(k + 3) << 12]);
        }
        float best = fminf(fminf(b0, b1), fminf(b2, b3));
        best = fminf(best, __shfl_xor_sync(0xffffffffu, best, 8));
        best = fminf(best, __shfl_xor_sync(0xffffffffu, best, 16));
        sd = (q == 0) ? best : 0.f;             // count each col once
    }
    __shared__ float rA[256];
    __shared__ float rB[256];
    rA[threadIdx.x] = sd;
    rB[threadIdx.x] = sn;
    __syncthreads();
    for (int s = 128; s > 0; s >>= 1) {
        if (threadIdx.x < s) {
            rA[threadIdx.x] += rA[threadIdx.x + s];
            rB[threadIdx.x] += rB[threadIdx.x + s];
        }
        __syncthreads();
    }
    __shared__ bool amlast;
    if (threadIdx.x == 0) {
        g_part[blockIdx.x * 2 + 0] = rA[0];
        g_part[blockIdx.x * 2 + 1] = rB[0];
        __threadfence();
        unsigned int tkt = atomicAdd(&g_cnt, 1u);
        amlast = (tkt == gridDim.x - 1);
    }
    __syncthreads();
    if (!amlast) return;

    // last block: fold NPOST block partials + 431 edge partials
    int t = threadIdx.x;
    float fd = g_part[t * 2] + g_part[(t + 256) * 2]
             + (t + 512 < NPOST ? g_part[(t + 512) * 2] : 0.f);
    float fn = g_part[t * 2 + 1] + g_part[(t + 256) * 2 + 1]
             + (t + 512 < NPOST ? g_part[(t + 512) * 2 + 1] : 0.f);
    float fe = (t < NFB ? g_edge[t] : 0.f) + (t + 256 < NFB ? g_edge[t + 256] : 0.f);
    rA[t] = fd; rB[t] = fn;
    __shared__ float rC[256];
    rC[t] = fe;
    __syncthreads();
    for (int s = 128; s > 0; s >>= 1) {
        if (t < s) { rA[t] += rA[t+s]; rB[t] += rB[t+s]; rC[t] += rC[t+s]; }
        __syncthreads();
    }
    if (t == 0) {
        double invBN = 1.0 / (double)(BB * NP);
        double cham  = (double)rA[0] * invBN;
        double nrm   = (double)rB[0] * invBN;
        double edge  = (double)rC[0] / (3.0 * (double)(BB * FF));
        out[0] = (float)(1.0 * cham + 0.1 * nrm + 0.5 * edge);
        g_cnt = 0;                   // reset for next graph replay
    }
}

// ---------------- launch ----------------
extern "C" void kernel_launch(void* const* d_in, const int* in_sizes, int n_in,
                              void* d_out, int out_size) {
    const float* pv = (const float*)d_in[0];   // predicted_vertices (B,V,3)
    const int*   pf = (const int*)  d_in[1];   // predicted_faces (F,3)
    // d_in[2], d_in[3] (gt mesh) unused by the reference computation
    const float* rp = (const float*)d_in[4];   // rand_pred (B,N,3)
    const float* rg = (const float*)d_in[5];   // rand_gt   (B,N,3)

    // idempotent, non-stream, capture-safe: raise dynamic smem cap for k_sample
    cudaFuncSetAttribute(k_sample, cudaFuncAttributeMaxDynamicSharedMemorySize,
                         (int)SMEM_CDF);

    k_faces<<<NFB, 256>>>(pv, pf);
    k_sample<<<dim3(16, BB, 2), 256, SMEM_CDF>>>(pv, pf, rp, rg);
    k_cham<<<dim3(RBLK, BB), 256>>>();
    k_post<<<NPOST, 256>>>((float*)d_out);
}

// round 16
// speedup vs baseline: 1.0446x; 1.0446x over previous
#include <cuda_runtime.h>
#include <math.h>

#define BB 8
#define VV 6890
#define FF 13776
#define NP 4096
#define EPSF 1e-12f
#define NC4 (FF / 4)                 // 3444 coarse CDF entries (stride 4)
#define NFB ((BB * FF + 255) / 256)  // 431 k_faces blocks
#define RBLK 128                     // row blocks per batch (4096/32)
#define NPOST ((5 * BB * NP) / 256)  // 640 k_post blocks (rows + 4x cols)

typedef unsigned long long ull;

// ---------------- device scratch (no allocations allowed) ----------------
__device__ float        g_cdf[BB * FF];            // per-face area -> CDF
__device__ float4       g_fn [BB * FF];            // per-face unit normals
__device__ float4       g_pts[2 * BB * NP];        // sampled points, w=|p|^2
__device__ float4       g_nrm[2 * BB * NP];        // sampled normals
__device__ unsigned int g_rowm[BB * NP];           // per-row mangled min (bits)
__device__ float        g_colp[BB * RBLK * NP];    // col-min partials (16.8MB)
__device__ float        g_edge[NFB];               // edge-loss block partials
__device__ float        g_part[2 * NPOST];         // k_post block partials (d,n)
__device__ unsigned int g_cnt;                     // last-block ticket (self-reset)

// ---------------- packed f32x2 helpers ----------------
__device__ __forceinline__ ull pk2(float lo, float hi) {
    ull r;
    asm("mov.b64 %0, {%1, %2};" : "=l"(r) : "f"(lo), "f"(hi));
    return r;
}
__device__ __forceinline__ float2 unpk(ull v) {
    float2 f;
    asm("mov.b64 {%0, %1}, %2;" : "=f"(f.x), "=f"(f.y) : "l"(v));
    return f;
}
__device__ __forceinline__ ull fma2(ull a, ull b, ull c) {
    ull d;
    asm("fma.rn.f32x2 %0, %1, %2, %3;" : "=l"(d) : "l"(a), "l"(b), "l"(c));
    return d;
}
__device__ __forceinline__ ull add2(ull a, ull b) {
    ull d;
    asm("add.rn.f32x2 %0, %1, %2;" : "=l"(d) : "l"(a), "l"(b));
    return d;
}
// packed min emulated with two scalar FMNMX on the register-pair halves
__device__ __forceinline__ ull min2(ull a, ull b) {
    float2 fa = unpk(a), fb = unpk(b);
    return pk2(fminf(fa.x, fb.x), fminf(fa.y, fb.y));
}
__device__ __forceinline__ ull shfl_xor64_w8(ull v, int m) {
    unsigned lo = (unsigned)v, hi = (unsigned)(v >> 32);
    lo = __shfl_xor_sync(0xffffffffu, lo, m, 8);
    hi = __shfl_xor_sync(0xffffffffu, hi, m, 8);
    return ((ull)hi << 32) | lo;
}

// ---------------- kernels ----------------

// Per (b,f): area, unit normal, edge partial per block.
__global__ void k_faces(const float* __restrict__ verts,
                        const int*   __restrict__ faces) {
    int id = blockIdx.x * blockDim.x + threadIdx.x;
    float esum = 0.f;
    if (id < BB * FF) {
        int b = id / FF, f = id % FF;
        int i0 = faces[f * 3 + 0];
        int i1 = faces[f * 3 + 1];
        int i2 = faces[f * 3 + 2];
        const float* vb = verts + (size_t)b * VV * 3;
        float ax = vb[i0*3+0], ay = vb[i0*3+1], az = vb[i0*3+2];
        float bx = vb[i1*3+0], by = vb[i1*3+1], bz = vb[i1*3+2];
        float cx = vb[i2*3+0], cy = vb[i2*3+1], cz = vb[i2*3+2];
        float ux = bx-ax, uy = by-ay, uz = bz-az;   // v1-v0
        float wx = cx-ax, wy = cy-ay, wz = cz-az;   // v2-v0
        float crx = uy*wz - uz*wy;
        float cry = uz*wx - ux*wz;
        float crz = ux*wy - uy*wx;
        float cn  = sqrtf(crx*crx + cry*cry + crz*crz);
        g_cdf[id] = 0.5f * cn;
        float inv = 1.f / (cn + EPSF);
        g_fn[id]  = make_float4(crx*inv, cry*inv, crz*inv, 0.f);
        float ex = bx-cx, ey = by-cy, ez = bz-cz;   // v1-v2
        esum = (ux*ux + uy*uy + uz*uz)
             + (ex*ex + ey*ey + ez*ez)
             + (wx*wx + wy*wy + wz*wz);
    }
    __shared__ float sred[256];
    sred[threadIdx.x] = esum;
    __syncthreads();
    for (int s = 128; s > 0; s >>= 1) {
        if (threadIdx.x < s) sred[threadIdx.x] += sred[threadIdx.x + s];
        __syncthreads();
    }
    if (threadIdx.x == 0) g_edge[blockIdx.x] = sred[0];
}

// Per-batch inclusive scan of areas -> normalized CDF. One block per batch.
__global__ void k_scan() {
    const int CH = (FF + 1023) / 1024;     // 14
    int b = blockIdx.x;
    int t = threadIdx.x;
    int lane = t & 31, warp = t >> 5;      // 32 warps
    float* a = g_cdf + (size_t)b * FF;
    int beg = t * CH;
    int end = min(beg + CH, FF);
    float loc[CH];
    float s = 0.f;
    for (int i = beg; i < end; i++) { s += a[i]; loc[i - beg] = s; }

    float ws = s;
    #pragma unroll
    for (int off = 1; off < 32; off <<= 1) {
        float v = __shfl_up_sync(0xffffffffu, ws, off);
        if (lane >= off) ws += v;
    }
    __shared__ float wsum[32];
    __shared__ float wpre[33];
    if (lane == 31) wsum[warp] = ws;
    __syncthreads();
    if (warp == 0) {
        float xs = wsum[lane];
        #pragma unroll
        for (int off = 1; off < 32; off <<= 1) {
            float v = __shfl_up_sync(0xffffffffu, xs, off);
            if (lane >= off) xs += v;
        }
        wpre[lane + 1] = xs;
        if (lane == 0) wpre[0] = 0.f;
    }
    __syncthreads();
    float total = wpre[32];
    float excl  = wpre[warp] + (ws - s);
    float scale = 1.f / (total + EPSF);
    for (int i = beg; i < end; i++) a[i] = (excl + loc[i - beg]) * scale;
}

// Sample points. grid (16 chunks, 8 batches, 2 sets), block 256.
__global__ void k_sample(const float* __restrict__ verts,
                         const int*   __restrict__ faces,
                         const float* __restrict__ rp,
                         const float* __restrict__ rg) {
    int set = blockIdx.z;
    int b   = blockIdx.y;
    int n   = blockIdx.x * 256 + threadIdx.x;
    const float* cdf = g_cdf + (size_t)b * FF;
    __shared__ float sc[NC4];
    for (int i = threadIdx.x; i < NC4; i += 256)
        sc[i] = cdf[i * 4 + 3];
    __syncthreads();

    const float* rnd = (set ? rg : rp) + ((size_t)b * NP + n) * 3;
    float u = rnd[0], r1 = rnd[1], r2 = rnd[2];

    int lo = 0, hi = NC4;
    while (lo < hi) {
        int m = (lo + hi) >> 1;
        if (sc[m] < u) lo = m + 1; else hi = m;
    }
    int idx;
    if (lo == NC4) {
        idx = FF - 1;
    } else {
        float4 seg = *(const float4*)&cdf[lo * 4];
        idx = lo * 4 + (seg.x < u) + (seg.y < u) + (seg.z < u);
    }
    int i0 = faces[idx*3+0], i1 = faces[idx*3+1], i2 = faces[idx*3+2];
    const float* vb = verts + (size_t)b * VV * 3;
    float su = sqrtf(r1);
    float w0 = 1.f - su;
    float w1 = su * (1.f - r2);
    float w2 = su * r2;
    float x = w0*vb[i0*3+0] + w1*vb[i1*3+0] + w2*vb[i2*3+0];
    float y = w0*vb[i0*3+1] + w1*vb[i1*3+1] + w2*vb[i2*3+1];
    float z = w0*vb[i0*3+2] + w1*vb[i1*3+2] + w2*vb[i2*3+2];
    int out = set * BB * NP + b * NP + n;
    g_pts[out] = make_float4(x, y, z, x*x + y*y + z*z);
    g_nrm[out] = g_fn[(size_t)b * FF + idx];
}

// Fused chamfer (proven R12 config): packed f32x2 FMA chain + double-buffered
// tiles + width-8 shuffle col reduce + plain float4 stores of col partials.
// grid (RBLK=128, BB), block 256: 32 rows x 4096 cols per block.
__global__ void __launch_bounds__(256) k_cham() {
    const int b   = blockIdx.y;
    const int rb  = blockIdx.x * 32;
    const int tid = threadIdx.x;
    const int tx  = tid >> 3;      // 0..31 col group
    const int ty  = tid & 7;       // 0..7 row group
    const float4* __restrict__ P = g_pts + (size_t)b * NP;
    const float4* __restrict__ Q = g_pts + BB * NP + (size_t)b * NP;

    __shared__ __align__(16) float sqx[2][128];
    __shared__ __align__(16) float sqy[2][128];
    __shared__ __align__(16) float sqz[2][128];
    __shared__ __align__(16) float sqw[2][128];
    __shared__ unsigned int srow[32][33];

    const ull INF2 = pk2(__int_as_float(0x7F800000), __int_as_float(0x7F800000));

    ull px2d[4], py2d[4], pz2d[4], pwd[4], rowb2[4];
    #pragma unroll
    for (int i = 0; i < 4; i++) {
        float4 p = P[rb + ty * 4 + i];
        float vx = -2.f * p.x, vy = -2.f * p.y, vz = -2.f * p.z;
        px2d[i] = pk2(vx, vx);
        py2d[i] = pk2(vy, vy);
        pz2d[i] = pk2(vz, vz);
        pwd[i]  = pk2(p.w, p.w);
        rowb2[i] = INF2;
    }
    ull cbase0 = ((ull)(unsigned)(tx * 4 + 1) << 32) | (unsigned)(tx * 4);
    ull cbase1 = cbase0 + 0x0000000200000002ULL;

    if (tid < 128) {
        float4 q = Q[tid];
        sqx[0][tid] = q.x; sqy[0][tid] = q.y; sqz[0][tid] = q.z; sqw[0][tid] = q.w;
    }
    __syncthreads();

    for (int t = 0; t < 32; t++) {
        float4 nq;
        if (t < 31 && tid < 128) nq = Q[(t + 1) * 128 + tid];
        const int cur = t & 1;
        ull ctpk  = (ull)(unsigned)(t * 128) * 0x0000000100000001ULL;
        ull colb0 = INF2, colb1 = INF2;

        {
            int c = tx * 4;
            ull qx0 = *(const ull*)&sqx[cur][c];
            ull qy0 = *(const ull*)&sqy[cur][c];
            ull qz0 = *(const ull*)&sqz[cur][c];
            ull qw0 = *(const ull*)&sqw[cur][c];
            ull qx1 = *(const ull*)&sqx[cur][c + 2];
            ull qy1 = *(const ull*)&sqy[cur][c + 2];
            ull qz1 = *(const ull*)&sqz[cur][c + 2];
            ull qw1 = *(const ull*)&sqw[cur][c + 2];
            ull cp0 = cbase0 + ctpk;
            ull cp1 = cbase1 + ctpk;
            #pragma unroll
            for (int i = 0; i < 4; i++) {
                ull d0 = add2(fma2(px2d[i], qx0,
                           fma2(py2d[i], qy0,
                           fma2(pz2d[i], qz0, qw0))), pwd[i]);
                ull m0 = (d0 & 0xFFFFF000FFFFF000ULL) | cp0;
                rowb2[i] = min2(rowb2[i], m0);
                colb0    = min2(colb0, d0);
                ull d1 = add2(fma2(px2d[i], qx1,
                           fma2(py2d[i], qy1,
                           fma2(pz2d[i], qz1, qw1))), pwd[i]);
                ull m1 = (d1 & 0xFFFFF000FFFFF000ULL) | cp1;
                rowb2[i] = min2(rowb2[i], m1);
                colb1    = min2(colb1, d1);
            }
        }
        colb0 = min2(colb0, shfl_xor64_w8(colb0, 4));
        colb0 = min2(colb0, shfl_xor64_w8(colb0, 2));
        colb0 = min2(colb0, shfl_xor64_w8(colb0, 1));
        colb1 = min2(colb1, shfl_xor64_w8(colb1, 4));
        colb1 = min2(colb1, shfl_xor64_w8(colb1, 2));
        colb1 = min2(colb1, shfl_xor64_w8(colb1, 1));
        if (ty == 0) {
            int base = ((b * RBLK + blockIdx.x) << 12) + t * 128 + tx * 4;
            float2 f0 = unpk(colb0), f1 = unpk(colb1);
            *(float4*)&g_colp[base] = make_float4(f0.x, f0.y, f1.x, f1.y);
        }
        if (t < 31 && tid < 128) {
            const int nb = (t + 1) & 1;
            sqx[nb][tid] = nq.x; sqy[nb][tid] = nq.y;
            sqz[nb][tid] = nq.z; sqw[nb][tid] = nq.w;
        }
        __syncthreads();
    }

    #pragma unroll
    for (int i = 0; i < 4; i++) {
        float2 f = unpk(rowb2[i]);
        srow[ty * 4 + i][tx] = __float_as_uint(fminf(f.x, f.y));
    }
    __syncthreads();
    if (tid < 32) {
        float best = __uint_as_float(srow[tid][0]);
        #pragma unroll
        for (int k = 1; k < 32; k++)
            best = fminf(best, __uint_as_float(srow[tid][k]));
        g_rowm[(size_t)b * NP + rb + tid] = __float_as_uint(best);
    }
}

// Rows: decode argmin, recompute exact distance + normal loss.
// Cols: quarter-per-warp mapping — each warp load is 32 consecutive floats
// (1 cache line); 8 independent accumulators; cross-quarter fold via smem.
// Blocks are uniformly row-only or col-only (BB*NP/256 = 128 exactly).
__global__ void k_post(float* out) {
    int gid = blockIdx.x * 256 + threadIdx.x;   // 0 .. 5*BB*NP
    float sd = 0.f, sn = 0.f;
    if (gid < BB * NP) {                        // rows -> dist1 + normals
        int b = gid >> 12;
        unsigned int m = g_rowm[gid];
        int col = m & 0xFFF;
        int qi  = BB * NP + (b << 12) + col;
        float4 p = g_pts[gid];
        float4 q = g_pts[qi];
        sd = p.w + q.w - 2.f * (p.x*q.x + p.y*q.y + p.z*q.z);
        float4 pn = g_nrm[gid];
        float4 qn = g_nrm[qi];
        sn = 1.f - fabsf(pn.x*qn.x + pn.y*qn.y + pn.z*qn.z);
    } else {                                    // cols -> dist2
        int lane = threadIdx.x & 31;
        int wb   = threadIdx.x >> 5;            // warp in block 0..7
        int w    = (gid - BB * NP) >> 5;        // global col-warp
        int group = w >> 2;                     // 0..1023 (32-col groups)
        int q     = wb & 3;                     // quarter (w&3 == wb&3)
        int flat  = group * 32 + lane;          // column (batch-flattened)
        int b = flat >> 12, col = flat & 4095;
        const float* cp = g_colp + ((size_t)(b * RBLK + q * 32) << 12) + col;
        float m0 = __int_as_float(0x7F800000), m1 = m0, m2 = m0, m3 = m0;
        float m4 = m0, m5 = m0, m6 = m0, m7 = m0;
        #pragma unroll
        for (int k = 0; k < 32; k += 8) {
            m0 = fminf(m0, cp[(size_t)(k + 0) << 12]);
            m1 = fminf(m1, cp[(size_t)(k + 1) << 12]);
            m2 = fminf(m2, cp[(size_t)(k + 2) << 12]);
            m3 = fminf(m3, cp[(size_t)(k + 3) << 12]);
            m4 = fminf(m4, cp[(size_t)(k + 4) << 12]);
            m5 = fminf(m5, cp[(size_t)(k + 5) << 12]);
            m6 = fminf(m6, cp[(size_t)(k + 6) << 12]);
            m7 = fminf(m7, cp[(size_t)(k + 7) << 12]);
        }
        float best = fminf(fminf(fminf(m0, m1), fminf(m2, m3)),
                           fminf(fminf(m4, m5), fminf(m6, m7)));
        __shared__ float sq[8][32];
        sq[wb][lane] = best;
        __syncthreads();
        if (q == 0) {
            int wg = wb & 4;                    // group base warp (0 or 4)
            sd = fminf(fminf(sq[wg][lane], sq[wg + 1][lane]),
                       fminf(sq[wg + 2][lane], sq[wg + 3][lane]));
        }
    }
    __shared__ float rA[256];
    __shared__ float rB[256];
    rA[threadIdx.x] = sd;
    rB[threadIdx.x] = sn;
    __syncthreads();
    for (int s = 128; s > 0; s >>= 1) {
        if (threadIdx.x < s) {
            rA[threadIdx.x] += rA[threadIdx.x + s];
            rB[threadIdx.x] += rB[threadIdx.x + s];
        }
        __syncthreads();
    }
    __shared__ bool amlast;
    if (threadIdx.x == 0) {
        g_part[blockIdx.x * 2 + 0] = rA[0];
        g_part[blockIdx.x * 2 + 1] = rB[0];
        __threadfence();
        unsigned int tkt = atomicAdd(&g_cnt, 1u);
        amlast = (tkt == gridDim.x - 1);
    }
    __syncthreads();
    if (!amlast) return;

    // last block: fold NPOST block partials + 431 edge partials
    int t = threadIdx.x;
    float fd = g_part[t * 2] + g_part[(t + 256) * 2]
             + (t + 512 < NPOST ? g_part[(t + 512) * 2] : 0.f);
    float fn = g_part[t * 2 + 1] + g_part[(t + 256) * 2 + 1]
             + (t + 512 < NPOST ? g_part[(t + 512) * 2 + 1] : 0.f);
    float fe = (t < NFB ? g_edge[t] : 0.f) + (t + 256 < NFB ? g_edge[t + 256] : 0.f);
    rA[t] = fd; rB[t] = fn;
    __shared__ float rC[256];
    rC[t] = fe;
    __syncthreads();
    for (int s = 128; s > 0; s >>= 1) {
        if (t < s) { rA[t] += rA[t+s]; rB[t] += rB[t+s]; rC[t] += rC[t+s]; }
        __syncthreads();
    }
    if (t == 0) {
        double invBN = 1.0 / (double)(BB * NP);
        double cham  = (double)rA[0] * invBN;
        double nrm   = (double)rB[0] * invBN;
        double edge  = (double)rC[0] / (3.0 * (double)(BB * FF));
        out[0] = (float)(1.0 * cham + 0.1 * nrm + 0.5 * edge);
        g_cnt = 0;                   // reset for next graph replay
    }
}

// ---------------- launch ----------------
extern "C" void kernel_launch(void* const* d_in, const int* in_sizes, int n_in,
                              void* d_out, int out_size) {
    const float* pv = (const float*)d_in[0];   // predicted_vertices (B,V,3)
    const int*   pf = (const int*)  d_in[1];   // predicted_faces (F,3)
    // d_in[2], d_in[3] (gt mesh) unused by the reference computation
    const float* rp = (const float*)d_in[4];   // rand_pred (B,N,3)
    const float* rg = (const float*)d_in[5];   // rand_gt   (B,N,3)

    k_faces<<<NFB, 256>>>(pv, pf);
    k_scan<<<BB, 1024>>>();
    k_sample<<<dim3(16, BB, 2), 256>>>(pv, pf, rp, rg);
    k_cham<<<dim3(RBLK, BB), 256>>>();
    k_post<<<NPOST, 256>>>((float*)d_out);
}